// round 7
// baseline (speedup 1.0000x reference)
#include <cuda_runtime.h>
#include <cuda_bf16.h>
#include <math.h>
#include <stdint.h>

#define NTOK 32768
#define HID  1024
#define NS   64
#define KTOT 3072

// ---------------------------------------------------------------------------
// Device scratch (no runtime allocation allowed)
// ---------------------------------------------------------------------------
__device__ float g_h [(size_t)NTOK * HID];
__device__ float g_hd[(size_t)NTOK * (HID / 2)];
// bf16 3-way splits of X = concat(x0,x1,x2): [NTOK][KTOT] each
__device__ __nv_bfloat16 g_xa[(size_t)NTOK * KTOT];
__device__ __nv_bfloat16 g_xb[(size_t)NTOK * KTOT];
__device__ __nv_bfloat16 g_xc[(size_t)NTOK * KTOT];
// bf16 splits of Wd1 [HID/2][KTOT]
__device__ __nv_bfloat16 g_wda[(size_t)(HID / 2) * KTOT];
__device__ __nv_bfloat16 g_wdb[(size_t)(HID / 2) * KTOT];
__device__ __nv_bfloat16 g_wdc[(size_t)(HID / 2) * KTOT];

__device__ __forceinline__ float gelu_exact(float x) {
    return 0.5f * x * (1.0f + erff(x * 0.70710678118654752440f));
}

// ===========================================================================
// PART 1: round-1 PROVEN scalar fp32 GEMM+GELU (verbatim) — probs path
// ===========================================================================
#define BM 128
#define BN 128
#define BK 16
#define TM 8
#define TN 8

__global__ __launch_bounds__(256, 2)
void gemm3_gelu_kernel(const float* __restrict__ x0,
                       const float* __restrict__ x1,
                       const float* __restrict__ x2,
                       const float* __restrict__ W,   // [Nout, KTOT]
                       const float* __restrict__ bias,
                       float* __restrict__ out,       // [NTOK, Nout]
                       int Nout)
{
    __shared__ float As[BK][BM];   // As[k][m]
    __shared__ float Bs[BK][BN];   // Bs[k][n]

    const int tid = threadIdx.x;             // 0..255
    const int m0  = blockIdx.y * BM;
    const int n0  = blockIdx.x * BN;
    const int ty  = tid / 16;                // 0..15
    const int tx  = tid % 16;                // 0..15

    float acc[TM][TN];
    #pragma unroll
    for (int i = 0; i < TM; i++)
        #pragma unroll
        for (int j = 0; j < TN; j++) acc[i][j] = 0.0f;

    for (int k0 = 0; k0 < KTOT; k0 += BK) {
        const int part = k0 / HID;
        const float* xp = (part == 0) ? x0 : ((part == 1) ? x1 : x2);
        const int kp = k0 - part * HID;

        #pragma unroll
        for (int p = 0; p < 2; p++) {
            const int slot = tid + p * 256;       // 0..511
            const int row  = slot >> 2;           // 0..127
            const int vc   = (slot & 3) * 4;      // 0,4,8,12

            float4 av = *reinterpret_cast<const float4*>(
                xp + (size_t)(m0 + row) * HID + kp + vc);
            As[vc + 0][row] = av.x;
            As[vc + 1][row] = av.y;
            As[vc + 2][row] = av.z;
            As[vc + 3][row] = av.w;

            float4 bv = *reinterpret_cast<const float4*>(
                W + (size_t)(n0 + row) * KTOT + k0 + vc);
            Bs[vc + 0][row] = bv.x;
            Bs[vc + 1][row] = bv.y;
            Bs[vc + 2][row] = bv.z;
            Bs[vc + 3][row] = bv.w;
        }
        __syncthreads();

        #pragma unroll
        for (int kk = 0; kk < BK; kk++) {
            float a[TM], b[TN];
            #pragma unroll
            for (int i = 0; i < TM; i++) a[i] = As[kk][ty * TM + i];
            #pragma unroll
            for (int j = 0; j < TN; j++) b[j] = Bs[kk][tx * TN + j];
            #pragma unroll
            for (int i = 0; i < TM; i++)
                #pragma unroll
                for (int j = 0; j < TN; j++)
                    acc[i][j] = fmaf(a[i], b[j], acc[i][j]);
        }
        __syncthreads();
    }

    float bj[TN];
    #pragma unroll
    for (int j = 0; j < TN; j++) bj[j] = bias[n0 + tx * TN + j];

    #pragma unroll
    for (int i = 0; i < TM; i++) {
        const size_t rowoff = (size_t)(m0 + ty * TM + i) * Nout + n0 + tx * TN;
        #pragma unroll
        for (int j = 0; j < TN; j++) {
            out[rowoff + j] = gelu_exact(acc[i][j] + bj[j]);
        }
    }
}

// ===========================================================================
// PART 2: bf16 6-term split mma GEMM — beta path this round (diagnostic)
// ===========================================================================
__device__ __forceinline__ void cp16(uint32_t dst_smem, const void* src) {
    asm volatile("cp.async.cg.shared.global [%0], [%1], 16;"
                 :: "r"(dst_smem), "l"(src));
}
#define CP_COMMIT() asm volatile("cp.async.commit_group;" ::: "memory")
#define CP_WAIT1()  asm volatile("cp.async.wait_group 1;" ::: "memory")

__device__ __forceinline__ void mma16(float* c, const uint32_t* a, const uint32_t* b) {
    asm volatile(
        "mma.sync.aligned.m16n8k16.row.col.f32.bf16.bf16.f32 "
        "{%0,%1,%2,%3}, {%4,%5,%6,%7}, {%8,%9}, {%0,%1,%2,%3};"
        : "+f"(c[0]), "+f"(c[1]), "+f"(c[2]), "+f"(c[3])
        : "r"(a[0]), "r"(a[1]), "r"(a[2]), "r"(a[3]), "r"(b[0]), "r"(b[1]));
}

// Exact 3-way bf16 decomposition: x == b1 + b2 + b3
__device__ __forceinline__ void bsplit3(float x, uint16_t& s1, uint16_t& s2, uint16_t& s3) {
    __nv_bfloat16 b1 = __float2bfloat16_rn(x);
    float r1 = x - __bfloat162float(b1);
    __nv_bfloat16 b2 = __float2bfloat16_rn(r1);
    float r2 = r1 - __bfloat162float(b2);
    __nv_bfloat16 b3 = __float2bfloat16_rn(r2);
    s1 = __bfloat16_as_ushort(b1);
    s2 = __bfloat16_as_ushort(b2);
    s3 = __bfloat16_as_ushort(b3);
}

__global__ __launch_bounds__(256)
void splitX_kernel(const float* __restrict__ in,
                   __nv_bfloat16* __restrict__ oa,
                   __nv_bfloat16* __restrict__ ob,
                   __nv_bfloat16* __restrict__ oc, int col0)
{
    const int idx4 = blockIdx.x * 256 + threadIdx.x;
    if (idx4 >= NTOK * HID / 4) return;
    const int n  = idx4 >> 8;
    const int c4 = idx4 & 255;
    float4 v = reinterpret_cast<const float4*>(in)[idx4];

    uint16_t a[4], b[4], c[4];
    bsplit3(v.x, a[0], b[0], c[0]);
    bsplit3(v.y, a[1], b[1], c[1]);
    bsplit3(v.z, a[2], b[2], c[2]);
    bsplit3(v.w, a[3], b[3], c[3]);

    const size_t off = (size_t)n * KTOT + col0 + c4 * 4;
    *reinterpret_cast<uint2*>(oa + off) =
        make_uint2((uint32_t)a[0] | ((uint32_t)a[1] << 16),
                   (uint32_t)a[2] | ((uint32_t)a[3] << 16));
    *reinterpret_cast<uint2*>(ob + off) =
        make_uint2((uint32_t)b[0] | ((uint32_t)b[1] << 16),
                   (uint32_t)b[2] | ((uint32_t)b[3] << 16));
    *reinterpret_cast<uint2*>(oc + off) =
        make_uint2((uint32_t)c[0] | ((uint32_t)c[1] << 16),
                   (uint32_t)c[2] | ((uint32_t)c[3] << 16));
}

__global__ __launch_bounds__(256)
void splitW_kernel(const float* __restrict__ in,
                   __nv_bfloat16* __restrict__ oa,
                   __nv_bfloat16* __restrict__ ob,
                   __nv_bfloat16* __restrict__ oc, int n4)
{
    const int idx4 = blockIdx.x * 256 + threadIdx.x;
    if (idx4 >= n4) return;
    float4 v = reinterpret_cast<const float4*>(in)[idx4];
    uint16_t a[4], b[4], c[4];
    bsplit3(v.x, a[0], b[0], c[0]);
    bsplit3(v.y, a[1], b[1], c[1]);
    bsplit3(v.z, a[2], b[2], c[2]);
    bsplit3(v.w, a[3], b[3], c[3]);
    const size_t off = (size_t)idx4 * 4;
    *reinterpret_cast<uint2*>(oa + off) =
        make_uint2((uint32_t)a[0] | ((uint32_t)a[1] << 16),
                   (uint32_t)a[2] | ((uint32_t)a[3] << 16));
    *reinterpret_cast<uint2*>(ob + off) =
        make_uint2((uint32_t)b[0] | ((uint32_t)b[1] << 16),
                   (uint32_t)b[2] | ((uint32_t)b[3] << 16));
    *reinterpret_cast<uint2*>(oc + off) =
        make_uint2((uint32_t)c[0] | ((uint32_t)c[1] << 16),
                   (uint32_t)c[2] | ((uint32_t)c[3] << 16));
}

// bf16 6-term GEMM: BM=BN=128, BK=32, 256 threads (4M x 2N warps)
#define RSW   20                        // words per smem row (16 data + 4 pad)
#define LVLW  (128 * RSW)
#define SWORDS (6 * LVLW)
#define NITER (KTOT / 32)
#define SMEM_MMA_BYTES (2 * SWORDS * 4)   // 122880

static __device__ __forceinline__ void fill_stage6(
    const __nv_bfloat16* __restrict__ xa, const __nv_bfloat16* __restrict__ xb,
    const __nv_bfloat16* __restrict__ xc,
    const __nv_bfloat16* __restrict__ wa, const __nv_bfloat16* __restrict__ wb,
    const __nv_bfloat16* __restrict__ wc,
    int m0, int n0, int k0, int tid, int stage, uint32_t sbase)
{
    const __nv_bfloat16* srcs[6] = {xa, xb, xc, wa, wb, wc};
    const int bases[2] = {m0, n0};
    #pragma unroll
    for (int p = 0; p < 12; p++) {
        const int slot = p >> 1;                // 0..5
        const int c    = tid + (p & 1) * 256;   // 0..511
        const int row  = c >> 2;
        const int q    = c & 3;
        const __nv_bfloat16* src = srcs[slot] +
            (size_t)(bases[slot / 3] + row) * KTOT + k0 + q * 8;
        const uint32_t dw = (uint32_t)(stage * SWORDS + slot * LVLW + row * RSW + q * 4);
        cp16(sbase + dw * 4u, src);
    }
}

__global__ void __launch_bounds__(256)
gemm_bf16x6_gelu(const __nv_bfloat16* __restrict__ xa,
                 const __nv_bfloat16* __restrict__ xb,
                 const __nv_bfloat16* __restrict__ xc,
                 const __nv_bfloat16* __restrict__ wa,
                 const __nv_bfloat16* __restrict__ wb,
                 const __nv_bfloat16* __restrict__ wc,
                 const float* __restrict__ bias,
                 float* __restrict__ out, int Nout)
{
    extern __shared__ uint32_t smw[];

    const int tid  = threadIdx.x;
    const int lane = tid & 31;
    const int wid  = tid >> 5;
    const int g    = lane >> 2;
    const int t    = lane & 3;
    const int warp_m = wid >> 1;
    const int warp_n = wid & 1;
    const int m0 = blockIdx.y * 128;
    const int n0 = blockIdx.x * 128;

    const uint32_t sbase = (uint32_t)__cvta_generic_to_shared(smw);

    float acc[2][8][4];
    #pragma unroll
    for (int mi = 0; mi < 2; mi++)
        #pragma unroll
        for (int ni = 0; ni < 8; ni++)
            #pragma unroll
            for (int q = 0; q < 4; q++) acc[mi][ni][q] = 0.0f;

    fill_stage6(xa, xb, xc, wa, wb, wc, m0, n0, 0, tid, 0, sbase);
    CP_COMMIT();
    fill_stage6(xa, xb, xc, wa, wb, wc, m0, n0, 32, tid, 1, sbase);
    CP_COMMIT();

    #pragma unroll 1
    for (int iter = 0; iter < NITER; iter++) {
        CP_WAIT1();
        __syncthreads();

        const int stage = iter & 1;
        const uint32_t* As = smw + stage * SWORDS + (warp_m * 32) * RSW;
        const uint32_t* Bs = smw + stage * SWORDS + 3 * LVLW + (warp_n * 64) * RSW;

        #pragma unroll
        for (int kc = 0; kc < 2; kc++) {
            const int w0 = kc * 8 + t;

            uint32_t af[3][2][4];
            #pragma unroll
            for (int l = 0; l < 3; l++)
                #pragma unroll
                for (int mi = 0; mi < 2; mi++) {
                    const uint32_t* Ap = As + l * LVLW + (mi * 16 + g) * RSW + w0;
                    af[l][mi][0] = Ap[0];
                    af[l][mi][1] = Ap[8 * RSW];
                    af[l][mi][2] = Ap[4];
                    af[l][mi][3] = Ap[8 * RSW + 4];
                }

            uint32_t bf_[3][8][2];
            #pragma unroll
            for (int l = 0; l < 3; l++)
                #pragma unroll
                for (int ni = 0; ni < 8; ni++) {
                    const uint32_t* Bp = Bs + l * LVLW + (ni * 8 + g) * RSW + w0;
                    bf_[l][ni][0] = Bp[0];
                    bf_[l][ni][1] = Bp[4];
                }

            #pragma unroll
            for (int mi = 0; mi < 2; mi++)
                #pragma unroll
                for (int ni = 0; ni < 8; ni++) {
                    mma16(acc[mi][ni], af[0][mi], bf_[0][ni]);   // (1,1)
                    mma16(acc[mi][ni], af[0][mi], bf_[1][ni]);   // (1,2)
                    mma16(acc[mi][ni], af[1][mi], bf_[0][ni]);   // (2,1)
                    mma16(acc[mi][ni], af[0][mi], bf_[2][ni]);   // (1,3)
                    mma16(acc[mi][ni], af[1][mi], bf_[1][ni]);   // (2,2)
                    mma16(acc[mi][ni], af[2][mi], bf_[0][ni]);   // (3,1)
                }
        }
        __syncthreads();

        if (iter + 2 < NITER) {
            fill_stage6(xa, xb, xc, wa, wb, wc,
                        m0, n0, (iter + 2) * 32, tid, stage, sbase);
        }
        CP_COMMIT();
    }

    #pragma unroll
    for (int mi = 0; mi < 2; mi++) {
        #pragma unroll
        for (int half = 0; half < 2; half++) {
            const int row = m0 + warp_m * 32 + mi * 16 + g + half * 8;
            #pragma unroll
            for (int ni = 0; ni < 8; ni++) {
                const int col = n0 + warp_n * 64 + ni * 8 + 2 * t;
                float2 b = *(const float2*)(bias + col);
                float2 r;
                r.x = gelu_exact(acc[mi][ni][half * 2 + 0] + b.x);
                r.y = gelu_exact(acc[mi][ni][half * 2 + 1] + b.y);
                *(float2*)(out + (size_t)row * Nout + col) = r;
            }
        }
    }
}

// ===========================================================================
// PART 3: logits -> top-2 -> softmax (verbatim round 1) + beta (verbatim)
// ===========================================================================
#define TTOK 8

__global__ __launch_bounds__(NS)
void logits_topk_kernel(const float* __restrict__ h,
                        const float* __restrict__ W2,
                        const float* __restrict__ b2,
                        float* __restrict__ probs)
{
    __shared__ float hs[TTOK][HID];
    __shared__ float lg[TTOK][NS];
    __shared__ float pv[TTOK][2];
    __shared__ int   pi[TTOK][2];

    const int n0 = blockIdx.x * TTOK;
    const int s  = threadIdx.x;

    {
        const float4* src = reinterpret_cast<const float4*>(h + (size_t)n0 * HID);
        float4* dst = reinterpret_cast<float4*>(&hs[0][0]);
        #pragma unroll
        for (int i = s; i < TTOK * HID / 4; i += NS) dst[i] = src[i];
    }
    __syncthreads();

    float acc[TTOK];
    #pragma unroll
    for (int tk = 0; tk < TTOK; tk++) acc[tk] = 0.0f;

    const float* w = W2 + (size_t)s * HID;
    for (int k = 0; k < HID; k += 4) {
        float4 wv = *reinterpret_cast<const float4*>(w + k);
        #pragma unroll
        for (int tk = 0; tk < TTOK; tk++) {
            acc[tk] = fmaf(wv.x, hs[tk][k + 0], acc[tk]);
            acc[tk] = fmaf(wv.y, hs[tk][k + 1], acc[tk]);
            acc[tk] = fmaf(wv.z, hs[tk][k + 2], acc[tk]);
            acc[tk] = fmaf(wv.w, hs[tk][k + 3], acc[tk]);
        }
    }
    const float bb = b2[s];
    #pragma unroll
    for (int tk = 0; tk < TTOK; tk++) lg[tk][s] = acc[tk] + bb;
    __syncthreads();

    if (s < TTOK) {
        float v1 = -3.4e38f, v2 = -3.4e38f;
        int   i1 = -1,       i2 = -1;
        #pragma unroll
        for (int j = 0; j < NS; j++) {
            float v = lg[s][j];
            if (v > v1)      { v2 = v1; i2 = i1; v1 = v; i1 = j; }
            else if (v > v2) { v2 = v;  i2 = j; }
        }
        const float e2  = expf(v2 - v1);
        const float inv = 1.0f / (1.0f + e2);
        pv[s][0] = inv;  pv[s][1] = e2 * inv;
        pi[s][0] = i1;   pi[s][1] = i2;
    }
    __syncthreads();

    #pragma unroll
    for (int tk = 0; tk < TTOK; tk++) {
        float p = 0.0f;
        if (s == pi[tk][0])      p = pv[tk][0];
        else if (s == pi[tk][1]) p = pv[tk][1];
        probs[(size_t)(n0 + tk) * NS + s] = p;
    }
}

__global__ __launch_bounds__(128)
void beta_kernel(const float* __restrict__ hd,
                 const float* __restrict__ Wd2,
                 const float* __restrict__ bd2,
                 float* __restrict__ beta)
{
    const int warp = threadIdx.x >> 5;
    const int lane = threadIdx.x & 31;
    const int n = blockIdx.x * 4 + warp;

    const float* row = hd + (size_t)n * (HID / 2);
    float acc = 0.0f;
    #pragma unroll
    for (int k = lane * 4; k < HID / 2; k += 128) {
        float4 a = *reinterpret_cast<const float4*>(row + k);
        float4 w = *reinterpret_cast<const float4*>(Wd2 + k);
        acc += a.x * w.x + a.y * w.y + a.z * w.z + a.w * w.w;
    }
    #pragma unroll
    for (int o = 16; o > 0; o >>= 1) acc += __shfl_xor_sync(0xffffffffu, acc, o);
    if (lane == 0) {
        float z = acc + bd2[0];
        beta[n] = 1.0f / (1.0f + expf(-z));
    }
}

// ---------------------------------------------------------------------------
extern "C" void kernel_launch(void* const* d_in, const int* in_sizes, int n_in,
                              void* d_out, int out_size)
{
    const float* sm  = (const float*)d_in[0];
    const float* tm  = (const float*)d_in[1];
    const float* dg  = (const float*)d_in[2];
    const float* W1  = (const float*)d_in[3];
    const float* b1  = (const float*)d_in[4];
    const float* W2  = (const float*)d_in[5];
    const float* b2  = (const float*)d_in[6];
    const float* Wd1 = (const float*)d_in[7];
    const float* bd1 = (const float*)d_in[8];
    const float* Wd2 = (const float*)d_in[9];
    const float* bd2 = (const float*)d_in[10];

    float* out   = (float*)d_out;
    float* probs = out;
    float* beta  = out + (size_t)NTOK * NS;

    float *hptr, *hdptr;
    __nv_bfloat16 *xa, *xb, *xc, *wda, *wdb, *wdc;
    cudaGetSymbolAddress((void**)&hptr,  g_h);
    cudaGetSymbolAddress((void**)&hdptr, g_hd);
    cudaGetSymbolAddress((void**)&xa,  g_xa);
    cudaGetSymbolAddress((void**)&xb,  g_xb);
    cudaGetSymbolAddress((void**)&xc,  g_xc);
    cudaGetSymbolAddress((void**)&wda, g_wda);
    cudaGetSymbolAddress((void**)&wdb, g_wdb);
    cudaGetSymbolAddress((void**)&wdc, g_wdc);

    cudaFuncSetAttribute(gemm_bf16x6_gelu,
                         cudaFuncAttributeMaxDynamicSharedMemorySize,
                         SMEM_MMA_BYTES);

    // GEMM1 (probs-critical): round-1 proven scalar fp32 path
    {
        dim3 grid(HID / BN, NTOK / BM);          // (8, 256)
        gemm3_gelu_kernel<<<grid, 256>>>(sm, tm, dg, W1, b1, hptr, HID);
    }

    // prep splits (overlaps nothing; ~0.2 ms)
    {
        const int nblk = (NTOK * HID / 4 + 255) / 256;
        splitX_kernel<<<nblk, 256>>>(sm, xa, xb, xc, 0);
        splitX_kernel<<<nblk, 256>>>(tm, xa, xb, xc, HID);
        splitX_kernel<<<nblk, 256>>>(dg, xa, xb, xc, 2 * HID);
        int n4 = (HID / 2) * KTOT / 4;
        splitW_kernel<<<(n4 + 255) / 256, 256>>>(Wd1, wda, wdb, wdc, n4);
    }

    // GEMMd (beta path, diagnostic): bf16 6-term mma
    {
        dim3 grid((HID / 2) / 128, NTOK / 128);  // (4, 256)
        gemm_bf16x6_gelu<<<grid, 256, SMEM_MMA_BYTES>>>(
            xa, xb, xc, wda, wdb, wdc, bd1, hdptr, HID / 2);
    }

    logits_topk_kernel<<<NTOK / TTOK, NS>>>(hptr, W2, b2, probs);
    beta_kernel<<<NTOK / 4, 128>>>(hdptr, Wd2, bd2, beta);
}

// round 8
// speedup vs baseline: 1.8127x; 1.8127x over previous
#include <cuda_runtime.h>
#include <cuda_bf16.h>
#include <math.h>
#include <stdint.h>

#define NTOK 32768
#define HID  1024
#define NS   64
#define KTOT 3072
#define TAU  1e-3f

// ------------------------- device scratch ---------------------------------
__device__ float g_h [(size_t)NTOK * HID];
__device__ float g_hd[(size_t)NTOK * (HID / 2)];
__device__ float g_hrep[(size_t)NTOK * HID];
__device__ __nv_bfloat16 g_xa[(size_t)NTOK * KTOT];
__device__ __nv_bfloat16 g_xb[(size_t)NTOK * KTOT];
__device__ __nv_bfloat16 g_w1a[(size_t)HID * KTOT];
__device__ __nv_bfloat16 g_w1b[(size_t)HID * KTOT];
__device__ __nv_bfloat16 g_wda[(size_t)(HID / 2) * KTOT];
__device__ __nv_bfloat16 g_wdb[(size_t)(HID / 2) * KTOT];
__device__ int g_nflag;
__device__ int g_flagidx[NTOK];

__device__ __forceinline__ float gelu_exact(float x) {
    return 0.5f * x * (1.0f + erff(x * 0.70710678118654752440f));
}
__device__ __forceinline__ void cp16(uint32_t d, const void* s) {
    asm volatile("cp.async.cg.shared.global [%0], [%1], 16;" :: "r"(d), "l"(s));
}
#define CP_COMMIT() asm volatile("cp.async.commit_group;" ::: "memory")
#define CP_WAIT1()  asm volatile("cp.async.wait_group 1;" ::: "memory")
__device__ __forceinline__ void mma16(float* c, const uint32_t* a, const uint32_t* b) {
    asm volatile("mma.sync.aligned.m16n8k16.row.col.f32.bf16.bf16.f32 "
        "{%0,%1,%2,%3}, {%4,%5,%6,%7}, {%8,%9}, {%0,%1,%2,%3};"
        : "+f"(c[0]), "+f"(c[1]), "+f"(c[2]), "+f"(c[3])
        : "r"(a[0]), "r"(a[1]), "r"(a[2]), "r"(a[3]), "r"(b[0]), "r"(b[1]));
}

// ---------------------- 2-level bf16 split prep ---------------------------
__device__ __forceinline__ void bsplit2(float x, uint16_t& s1, uint16_t& s2) {
    __nv_bfloat16 b1 = __float2bfloat16_rn(x);
    __nv_bfloat16 b2 = __float2bfloat16_rn(x - __bfloat162float(b1));
    s1 = __bfloat16_as_ushort(b1);
    s2 = __bfloat16_as_ushort(b2);
}

__global__ __launch_bounds__(256)
void splitX2(const float* __restrict__ in, __nv_bfloat16* __restrict__ oa,
             __nv_bfloat16* __restrict__ ob, int col0)
{
    const int idx4 = blockIdx.x * 256 + threadIdx.x;
    if (idx4 >= NTOK * HID / 4) return;
    const int n = idx4 >> 8, c4 = idx4 & 255;
    float4 v = reinterpret_cast<const float4*>(in)[idx4];
    uint16_t a[4], b[4];
    bsplit2(v.x, a[0], b[0]); bsplit2(v.y, a[1], b[1]);
    bsplit2(v.z, a[2], b[2]); bsplit2(v.w, a[3], b[3]);
    const size_t off = (size_t)n * KTOT + col0 + c4 * 4;
    *reinterpret_cast<uint2*>(oa + off) =
        make_uint2((uint32_t)a[0] | ((uint32_t)a[1] << 16),
                   (uint32_t)a[2] | ((uint32_t)a[3] << 16));
    *reinterpret_cast<uint2*>(ob + off) =
        make_uint2((uint32_t)b[0] | ((uint32_t)b[1] << 16),
                   (uint32_t)b[2] | ((uint32_t)b[3] << 16));
}

__global__ __launch_bounds__(256)
void splitW2(const float* __restrict__ in, __nv_bfloat16* __restrict__ oa,
             __nv_bfloat16* __restrict__ ob, int n4)
{
    const int idx4 = blockIdx.x * 256 + threadIdx.x;
    if (idx4 >= n4) return;
    float4 v = reinterpret_cast<const float4*>(in)[idx4];
    uint16_t a[4], b[4];
    bsplit2(v.x, a[0], b[0]); bsplit2(v.y, a[1], b[1]);
    bsplit2(v.z, a[2], b[2]); bsplit2(v.w, a[3], b[3]);
    const size_t off = (size_t)idx4 * 4;
    *reinterpret_cast<uint2*>(oa + off) =
        make_uint2((uint32_t)a[0] | ((uint32_t)a[1] << 16),
                   (uint32_t)a[2] | ((uint32_t)a[3] << 16));
    *reinterpret_cast<uint2*>(ob + off) =
        make_uint2((uint32_t)b[0] | ((uint32_t)b[1] << 16),
                   (uint32_t)b[2] | ((uint32_t)b[3] << 16));
}

// -------------- bf16 3-term mma GEMM (proven skeleton, L=2) ---------------
#define RSW   20
#define LVLW  (128 * RSW)
#define SWORDS (4 * LVLW)
#define NITER (KTOT / 32)
#define SMEM_MMA_BYTES (2 * SWORDS * 4)   // 81920

static __device__ __forceinline__ void fill_stage4(
    const __nv_bfloat16* __restrict__ xa, const __nv_bfloat16* __restrict__ xb,
    const __nv_bfloat16* __restrict__ wa, const __nv_bfloat16* __restrict__ wb,
    int m0, int n0, int k0, int tid, int stage, uint32_t sbase)
{
    const __nv_bfloat16* srcs[4] = {xa, xb, wa, wb};
    #pragma unroll
    for (int p = 0; p < 8; p++) {
        const int slot = p >> 1;
        const int c    = tid + (p & 1) * 256;
        const int row  = c >> 2;
        const int q    = c & 3;
        const int base = (slot < 2) ? m0 : n0;
        const __nv_bfloat16* src = srcs[slot] + (size_t)(base + row) * KTOT + k0 + q * 8;
        const uint32_t dw = (uint32_t)(stage * SWORDS + slot * LVLW + row * RSW + q * 4);
        cp16(sbase + dw * 4u, src);
    }
}

__global__ void __launch_bounds__(256)
gemm_bf16x3_gelu(const __nv_bfloat16* __restrict__ xa,
                 const __nv_bfloat16* __restrict__ xb,
                 const __nv_bfloat16* __restrict__ wa,
                 const __nv_bfloat16* __restrict__ wb,
                 const float* __restrict__ bias,
                 float* __restrict__ out, int Nout)
{
    extern __shared__ uint32_t smw[];
    const int tid  = threadIdx.x;
    const int lane = tid & 31;
    const int wid  = tid >> 5;
    const int g    = lane >> 2;
    const int t    = lane & 3;
    const int warp_m = wid >> 1;
    const int warp_n = wid & 1;
    const int m0 = blockIdx.y * 128;
    const int n0 = blockIdx.x * 128;
    const uint32_t sbase = (uint32_t)__cvta_generic_to_shared(smw);

    float acc[2][8][4];
    #pragma unroll
    for (int mi = 0; mi < 2; mi++)
        #pragma unroll
        for (int ni = 0; ni < 8; ni++)
            #pragma unroll
            for (int q = 0; q < 4; q++) acc[mi][ni][q] = 0.0f;

    fill_stage4(xa, xb, wa, wb, m0, n0, 0, tid, 0, sbase);
    CP_COMMIT();
    fill_stage4(xa, xb, wa, wb, m0, n0, 32, tid, 1, sbase);
    CP_COMMIT();

    #pragma unroll 1
    for (int iter = 0; iter < NITER; iter++) {
        CP_WAIT1();
        __syncthreads();
        const int stage = iter & 1;
        const uint32_t* As = smw + stage * SWORDS + (warp_m * 32) * RSW;
        const uint32_t* Bs = smw + stage * SWORDS + 2 * LVLW + (warp_n * 64) * RSW;

        #pragma unroll
        for (int kc = 0; kc < 2; kc++) {
            const int w0 = kc * 8 + t;
            uint32_t af[2][2][4];
            #pragma unroll
            for (int l = 0; l < 2; l++)
                #pragma unroll
                for (int mi = 0; mi < 2; mi++) {
                    const uint32_t* Ap = As + l * LVLW + (mi * 16 + g) * RSW + w0;
                    af[l][mi][0] = Ap[0];
                    af[l][mi][1] = Ap[8 * RSW];
                    af[l][mi][2] = Ap[4];
                    af[l][mi][3] = Ap[8 * RSW + 4];
                }
            uint32_t bf_[2][8][2];
            #pragma unroll
            for (int l = 0; l < 2; l++)
                #pragma unroll
                for (int ni = 0; ni < 8; ni++) {
                    const uint32_t* Bp = Bs + l * LVLW + (ni * 8 + g) * RSW + w0;
                    bf_[l][ni][0] = Bp[0];
                    bf_[l][ni][1] = Bp[4];
                }
            #pragma unroll
            for (int mi = 0; mi < 2; mi++)
                #pragma unroll
                for (int ni = 0; ni < 8; ni++) {
                    mma16(acc[mi][ni], af[0][mi], bf_[0][ni]);
                    mma16(acc[mi][ni], af[0][mi], bf_[1][ni]);
                    mma16(acc[mi][ni], af[1][mi], bf_[0][ni]);
                }
        }
        __syncthreads();
        if (iter + 2 < NITER)
            fill_stage4(xa, xb, wa, wb, m0, n0, (iter + 2) * 32, tid, stage, sbase);
        CP_COMMIT();
    }

    #pragma unroll
    for (int mi = 0; mi < 2; mi++)
        #pragma unroll
        for (int half = 0; half < 2; half++) {
            const int row = m0 + warp_m * 32 + mi * 16 + g + half * 8;
            #pragma unroll
            for (int ni = 0; ni < 8; ni++) {
                const int col = n0 + warp_n * 64 + ni * 8 + 2 * t;
                float2 b = *(const float2*)(bias + col);
                float2 r;
                r.x = gelu_exact(acc[mi][ni][half * 2 + 0] + b.x);
                r.y = gelu_exact(acc[mi][ni][half * 2 + 1] + b.y);
                *(float2*)(out + (size_t)row * Nout + col) = r;
            }
        }
}

// ------- repair GEMM: bit-identical round-1 scalar, row-gathered ----------
#define BM 128
#define BN 128
#define BK 16
#define TM 8
#define TN 8

__global__ __launch_bounds__(256, 2)
void gemm_repair(const float* __restrict__ x0, const float* __restrict__ x1,
                 const float* __restrict__ x2, const float* __restrict__ W,
                 const float* __restrict__ bias, float* __restrict__ out)
{
    const int nflag = g_nflag;
    const int m0 = blockIdx.y * BM;
    if (m0 >= nflag) return;
    __shared__ float As[BK][BM];
    __shared__ float Bs[BK][BN];

    const int tid = threadIdx.x;
    const int n0  = blockIdx.x * BN;
    const int ty  = tid / 16;
    const int tx  = tid % 16;

    float acc[TM][TN];
    #pragma unroll
    for (int i = 0; i < TM; i++)
        #pragma unroll
        for (int j = 0; j < TN; j++) acc[i][j] = 0.0f;

    for (int k0 = 0; k0 < KTOT; k0 += BK) {
        const int part = k0 / HID;
        const float* xp = (part == 0) ? x0 : ((part == 1) ? x1 : x2);
        const int kp = k0 - part * HID;

        #pragma unroll
        for (int p = 0; p < 2; p++) {
            const int slot = tid + p * 256;
            const int row  = slot >> 2;
            const int vc   = (slot & 3) * 4;
            const int cr   = (m0 + row < nflag) ? (m0 + row) : 0;
            const int grow = g_flagidx[cr];
            float4 av = *reinterpret_cast<const float4*>(
                xp + (size_t)grow * HID + kp + vc);
            As[vc + 0][row] = av.x; As[vc + 1][row] = av.y;
            As[vc + 2][row] = av.z; As[vc + 3][row] = av.w;
            float4 bv = *reinterpret_cast<const float4*>(
                W + (size_t)(n0 + row) * KTOT + k0 + vc);
            Bs[vc + 0][row] = bv.x; Bs[vc + 1][row] = bv.y;
            Bs[vc + 2][row] = bv.z; Bs[vc + 3][row] = bv.w;
        }
        __syncthreads();

        #pragma unroll
        for (int kk = 0; kk < BK; kk++) {
            float a[TM], b[TN];
            #pragma unroll
            for (int i = 0; i < TM; i++) a[i] = As[kk][ty * TM + i];
            #pragma unroll
            for (int j = 0; j < TN; j++) b[j] = Bs[kk][tx * TN + j];
            #pragma unroll
            for (int i = 0; i < TM; i++)
                #pragma unroll
                for (int j = 0; j < TN; j++)
                    acc[i][j] = fmaf(a[i], b[j], acc[i][j]);
        }
        __syncthreads();
    }

    float bj[TN];
    #pragma unroll
    for (int j = 0; j < TN; j++) bj[j] = bias[n0 + tx * TN + j];
    #pragma unroll
    for (int i = 0; i < TM; i++) {
        const int crow = m0 + ty * TM + i;
        if (crow < nflag) {
            const size_t ro = (size_t)crow * HID + n0 + tx * TN;
            #pragma unroll
            for (int j = 0; j < TN; j++)
                out[ro + j] = gelu_exact(acc[i][j] + bj[j]);
        }
    }
}

// ----------------------- logits kernels -----------------------------------
#define TTOK 8

__global__ void zero_flags_kernel() { if (threadIdx.x == 0) g_nflag = 0; }

template<bool FLAG>
__global__ __launch_bounds__(NS)
void logits_topk_kernel(const float* __restrict__ h,    // FLAG: g_h, else g_hrep
                        const float* __restrict__ W2,
                        const float* __restrict__ b2,
                        float* __restrict__ probs)
{
    __shared__ float hs[TTOK][HID];
    __shared__ float lg[TTOK][NS];
    __shared__ float pv[TTOK][2];
    __shared__ int   pi[TTOK][2];

    const int n0 = blockIdx.x * TTOK;
    if (!FLAG && n0 >= g_nflag) return;
    const int s  = threadIdx.x;

    {
        const float4* src = reinterpret_cast<const float4*>(h + (size_t)n0 * HID);
        float4* dst = reinterpret_cast<float4*>(&hs[0][0]);
        #pragma unroll
        for (int i = s; i < TTOK * HID / 4; i += NS) dst[i] = src[i];
    }
    __syncthreads();

    float acc[TTOK];
    #pragma unroll
    for (int tk = 0; tk < TTOK; tk++) acc[tk] = 0.0f;
    const float* w = W2 + (size_t)s * HID;
    for (int k = 0; k < HID; k += 4) {
        float4 wv = *reinterpret_cast<const float4*>(w + k);
        #pragma unroll
        for (int tk = 0; tk < TTOK; tk++) {
            acc[tk] = fmaf(wv.x, hs[tk][k + 0], acc[tk]);
            acc[tk] = fmaf(wv.y, hs[tk][k + 1], acc[tk]);
            acc[tk] = fmaf(wv.z, hs[tk][k + 2], acc[tk]);
            acc[tk] = fmaf(wv.w, hs[tk][k + 3], acc[tk]);
        }
    }
    const float bb = b2[s];
    #pragma unroll
    for (int tk = 0; tk < TTOK; tk++) lg[tk][s] = acc[tk] + bb;
    __syncthreads();

    if (s < TTOK) {
        float v1 = -3.4e38f, v2 = -3.4e38f, v3 = -3.4e38f;
        int   i1 = -1,       i2 = -1;
        #pragma unroll
        for (int j = 0; j < NS; j++) {
            float v = lg[s][j];
            if (v > v1)      { v3 = v2; v2 = v1; i2 = i1; v1 = v; i1 = j; }
            else if (v > v2) { v3 = v2; v2 = v;  i2 = j; }
            else if (v > v3) { v3 = v; }
        }
        const float e2  = expf(v2 - v1);
        const float inv = 1.0f / (1.0f + e2);
        pv[s][0] = inv;  pv[s][1] = e2 * inv;
        pi[s][0] = i1;   pi[s][1] = i2;
        if (FLAG && (v2 - v3 < TAU)) {
            int pos = atomicAdd(&g_nflag, 1);
            g_flagidx[pos] = n0 + s;
        }
    }
    __syncthreads();

    const int nflag = FLAG ? 0 : g_nflag;
    #pragma unroll
    for (int tk = 0; tk < TTOK; tk++) {
        float p = 0.0f;
        if (s == pi[tk][0])      p = pv[tk][0];
        else if (s == pi[tk][1]) p = pv[tk][1];
        if (FLAG) {
            probs[(size_t)(n0 + tk) * NS + s] = p;
        } else if (n0 + tk < nflag) {
            probs[(size_t)g_flagidx[n0 + tk] * NS + s] = p;
        }
    }
}

// ------------------------------ beta --------------------------------------
__global__ __launch_bounds__(128)
void beta_kernel(const float* __restrict__ hd, const float* __restrict__ Wd2,
                 const float* __restrict__ bd2, float* __restrict__ beta)
{
    const int warp = threadIdx.x >> 5;
    const int lane = threadIdx.x & 31;
    const int n = blockIdx.x * 4 + warp;
    const float* row = hd + (size_t)n * (HID / 2);
    float acc = 0.0f;
    #pragma unroll
    for (int k = lane * 4; k < HID / 2; k += 128) {
        float4 a = *reinterpret_cast<const float4*>(row + k);
        float4 w = *reinterpret_cast<const float4*>(Wd2 + k);
        acc += a.x * w.x + a.y * w.y + a.z * w.z + a.w * w.w;
    }
    #pragma unroll
    for (int o = 16; o > 0; o >>= 1) acc += __shfl_xor_sync(0xffffffffu, acc, o);
    if (lane == 0) beta[n] = 1.0f / (1.0f + expf(-(acc + bd2[0])));
}

// ---------------------------------------------------------------------------
extern "C" void kernel_launch(void* const* d_in, const int* in_sizes, int n_in,
                              void* d_out, int out_size)
{
    const float* sm  = (const float*)d_in[0];
    const float* tm  = (const float*)d_in[1];
    const float* dg  = (const float*)d_in[2];
    const float* W1  = (const float*)d_in[3];
    const float* b1  = (const float*)d_in[4];
    const float* W2  = (const float*)d_in[5];
    const float* b2  = (const float*)d_in[6];
    const float* Wd1 = (const float*)d_in[7];
    const float* bd1 = (const float*)d_in[8];
    const float* Wd2 = (const float*)d_in[9];
    const float* bd2 = (const float*)d_in[10];

    float* out   = (float*)d_out;
    float* probs = out;
    float* beta  = out + (size_t)NTOK * NS;

    float *hptr, *hdptr, *hrep;
    __nv_bfloat16 *xa, *xb, *w1a, *w1b, *wda, *wdb;
    cudaGetSymbolAddress((void**)&hptr,  g_h);
    cudaGetSymbolAddress((void**)&hdptr, g_hd);
    cudaGetSymbolAddress((void**)&hrep,  g_hrep);
    cudaGetSymbolAddress((void**)&xa,  g_xa);
    cudaGetSymbolAddress((void**)&xb,  g_xb);
    cudaGetSymbolAddress((void**)&w1a, g_w1a);
    cudaGetSymbolAddress((void**)&w1b, g_w1b);
    cudaGetSymbolAddress((void**)&wda, g_wda);
    cudaGetSymbolAddress((void**)&wdb, g_wdb);

    cudaFuncSetAttribute(gemm_bf16x3_gelu,
                         cudaFuncAttributeMaxDynamicSharedMemorySize,
                         SMEM_MMA_BYTES);

    zero_flags_kernel<<<1, 32>>>();

    // splits
    {
        const int nblk = (NTOK * HID / 4 + 255) / 256;
        splitX2<<<nblk, 256>>>(sm, xa, xb, 0);
        splitX2<<<nblk, 256>>>(tm, xa, xb, HID);
        splitX2<<<nblk, 256>>>(dg, xa, xb, 2 * HID);
        int n4 = HID * KTOT / 4;
        splitW2<<<(n4 + 255) / 256, 256>>>(W1, w1a, w1b, n4);
        n4 = (HID / 2) * KTOT / 4;
        splitW2<<<(n4 + 255) / 256, 256>>>(Wd1, wda, wdb, n4);
    }

    // GEMM1 (mma, 3-term) and GEMMd (mma, 3-term)
    {
        dim3 g1(HID / 128, NTOK / 128);
        gemm_bf16x3_gelu<<<g1, 256, SMEM_MMA_BYTES>>>(xa, xb, w1a, w1b, b1, hptr, HID);
        dim3 gd((HID / 2) / 128, NTOK / 128);
        gemm_bf16x3_gelu<<<gd, 256, SMEM_MMA_BYTES>>>(xa, xb, wda, wdb, bd1, hdptr, HID / 2);
    }

    // logits + top2 + flag near-ties
    logits_topk_kernel<true><<<NTOK / TTOK, NS>>>(hptr, W2, b2, probs);

    // repair flagged tokens: round-1-identical scalar chain
    {
        dim3 gr(HID / BN, NTOK / BM);
        gemm_repair<<<gr, 256>>>(sm, tm, dg, W1, b1, hrep);
        logits_topk_kernel<false><<<NTOK / TTOK, NS>>>(hrep, W2, b2, probs);
    }

    beta_kernel<<<NTOK / 4, 128>>>(hdptr, Wd2, bd2, beta);
}